// round 14
// baseline (speedup 1.0000x reference)
#include <cuda_runtime.h>
#include <cuda_fp16.h>
#include <cstdint>

// ---------------- problem constants ----------------
#define T_TOK   32768            // B*S tokens
#define NXD     1024             // feature dim (K)
#define A_CNT   20
#define H_CNT   50
#define O_CNT   3
#define NC      1000             // A_CNT*H_CNT real columns
#define NPAD    1024             // padded N
#define S_LEN   2048
#define LN_EPS  1e-5f
#define KB_OFF  8                // k-chunks for k_off partials

// fused-pre grid ranges
#define NB_SPLIT (T_TOK / 8)                 // 4096
#define NB_PREPB NPAD                        // 1024
#define NB_OFF1  (A_CNT * KB_OFF)            // 160
#define NB_PRE   (NB_SPLIT + NB_PREPB + NB_OFF1)

// ---------------- device scratch ----------------
__device__ float g_off[NC];
__device__ float g_offp[A_CNT * KB_OFF * H_CNT];             // k_off partials
__device__ float g_obuf[2][(size_t)T_TOK * 60];              // partial o, 2 slots
__device__ __align__(16) __half g_A[(size_t)T_TOK * NXD];    // 64 MB  xn fp16
__device__ __align__(16) __half g_B[(size_t)NPAD * NXD];     // 2 MB   (ln_g*W1)^T fp16

__device__ __forceinline__ uint32_t s2u(const void* p) {
    uint32_t a;
    asm("{ .reg .u64 t; cvta.to.shared.u64 t, %1; cvt.u32.u64 %0, t; }"
        : "=r"(a) : "l"(p));
    return a;
}
__device__ __forceinline__ unsigned pk2h(__half a, __half b) {
    return (unsigned)__half_as_ushort(a) | ((unsigned)__half_as_ushort(b) << 16);
}

#define CP16(saddr, gaddr) \
    asm volatile("cp.async.cg.shared.global [%0], [%1], 16;" :: "r"(saddr), "l"(gaddr))
#define CP_COMMIT() asm volatile("cp.async.commit_group;" ::: "memory")
#define CP_WAIT0()  asm volatile("cp.async.wait_group 0;" ::: "memory")

#define LDSM4(r, addr) \
    asm volatile("ldmatrix.sync.aligned.m8n8.x4.shared.b16 {%0,%1,%2,%3}, [%4];" \
        : "=r"((r)[0]), "=r"((r)[1]), "=r"((r)[2]), "=r"((r)[3]) : "r"(addr))

// f16-accumulate MMA: fresh chain start (C = 0)
#define MMAH16_Z(d, a, b0, b1) \
    asm volatile("mma.sync.aligned.m16n8k16.row.col.f16.f16.f16.f16 " \
        "{%0,%1}, {%2,%3,%4,%5}, {%6,%7}, {%8,%9};" \
        : "=r"((d)[0]), "=r"((d)[1]) \
        : "r"((a)[0]), "r"((a)[1]), "r"((a)[2]), "r"((a)[3]), \
          "r"(b0), "r"(b1), "r"(0u), "r"(0u))

// f16-accumulate MMA: chained (D = A*B + D)
#define MMAH16_C(d, a, b0, b1) \
    asm volatile("mma.sync.aligned.m16n8k16.row.col.f16.f16.f16.f16 " \
        "{%0,%1}, {%2,%3,%4,%5}, {%6,%7}, {%0,%1};" \
        : "+r"((d)[0]), "+r"((d)[1]) \
        : "r"((a)[0]), "r"((a)[1]), "r"((a)[2]), "r"((a)[3]), \
          "r"(b0), "r"(b1))

// =====================================================================
// K1 (fused pre): blockIdx ranges do LN-split | prepB | off1 concurrently
// =====================================================================
__global__ void __launch_bounds__(256) k_pre(const float* __restrict__ x,
                                             const float* __restrict__ ln_g,
                                             const float* __restrict__ ln_b,
                                             const float* __restrict__ W1) {
    const int blk = blockIdx.x;

    if (blk < NB_SPLIT) {
        const int w = threadIdx.x >> 5, l = threadIdx.x & 31;
        const int t = blk * 8 + w;
        const float4* xv = reinterpret_cast<const float4*>(x) + (size_t)t * 256;
        float4 v[8];
        float s = 0.f, q = 0.f;
        #pragma unroll
        for (int j = 0; j < 8; j++) {
            v[j] = xv[l + 32 * j];
            s += v[j].x + v[j].y + v[j].z + v[j].w;
            q += v[j].x * v[j].x + v[j].y * v[j].y + v[j].z * v[j].z + v[j].w * v[j].w;
        }
        #pragma unroll
        for (int o = 16; o > 0; o >>= 1) {
            s += __shfl_xor_sync(0xffffffffu, s, o);
            q += __shfl_xor_sync(0xffffffffu, q, o);
        }
        const float mu  = s * (1.0f / (float)NXD);
        const float var = fmaxf(q * (1.0f / (float)NXD) - mu * mu, 0.0f);
        const float rs  = 1.0f / sqrtf(var + LN_EPS);
        uint2* dst = reinterpret_cast<uint2*>(g_A) + (size_t)t * 256;
        #pragma unroll
        for (int j = 0; j < 8; j++) {
            uint2 H;
            H.x = pk2h(__float2half((v[j].x - mu) * rs), __float2half((v[j].y - mu) * rs));
            H.y = pk2h(__float2half((v[j].z - mu) * rs), __float2half((v[j].w - mu) * rs));
            dst[l + 32 * j] = H;
        }
    } else if (blk < NB_SPLIT + NB_PREPB) {
        const int n = blk - NB_SPLIT;
        int a = 0, h = 0;
        const bool val = (n < NC);
        if (val) { a = n / H_CNT; h = n - a * H_CNT; }
        #pragma unroll
        for (int j = 0; j < 4; j++) {
            const int k = threadIdx.x + j * 256;
            float wv = val ? ln_g[a * NXD + k] * W1[((size_t)a * NXD + k) * H_CNT + h] : 0.0f;
            g_B[(size_t)n * NXD + k] = __float2half(wv);
        }
    } else {
        __shared__ float red[5][H_CNT];
        const int idx = blk - NB_SPLIT - NB_PREPB;
        const int a  = idx / KB_OFF;
        const int kb = idx - a * KB_OFF;
        const int tid = threadIdx.x;
        const int g = tid / H_CNT, h = tid - g * H_CNT;
        float acc = 0.0f;
        if (g < 5) {
            const int n0 = kb * 128;
            for (int r = g; r < 128; r += 5) {
                const int n = n0 + r;
                acc += ln_b[a * NXD + n] * W1[((size_t)a * NXD + n) * H_CNT + h];
            }
            red[g][h] = acc;
        }
        __syncthreads();
        if (tid < H_CNT) {
            float sv = red[0][tid] + red[1][tid] + red[2][tid] + red[3][tid] + red[4][tid];
            g_offp[(a * KB_OFF + kb) * H_CNT + tid] = sv;
        }
    }
}

// =====================================================================
// K2: reduce off partials + b1 -> g_off
// =====================================================================
__global__ void __launch_bounds__(256) k_off2(const float* __restrict__ b1) {
    const int p = blockIdx.x * 256 + threadIdx.x;
    if (p >= NC) return;
    const int a = p / H_CNT, h = p - a * H_CNT;
    float s = 0.0f;
    #pragma unroll
    for (int kb = 0; kb < KB_OFF; kb++)
        s += g_offp[(a * KB_OFF + kb) * H_CNT + h];
    g_off[p] = s + b1[p];
}

// =====================================================================
// K3: fp16 mma.sync GEMM (f16 ACCUMULATE, per-kt fp32 spill)
//   CTA 128x128, BK=64, 8 warps (2Mx4N), warp tile 64x32, 2-stage.
//   Per kt: chain 4 MMAs in fp16 (zero-C start), convert-add -> fp32 acc.
// =====================================================================
#define SSTR   144
#define TILE_B (128 * SSTR)          // 18432
#define STAGE  (2 * TILE_B)          // 36864
#define SMEMT  (2 * STAGE)           // 73728
#define NKT    16
#define HS     136                   // epilogue h-stage stride (halfs)

__global__ void __launch_bounds__(256) k_gemm(const float* __restrict__ W2) {
    extern __shared__ __align__(16) char smem[];
    const uint32_t sb = s2u(smem);
    const int tid = threadIdx.x;
    const int w = tid >> 5, l = tid & 31;
    const int wm = w & 1, wn = w >> 1;          // 2(M) x 4(N), warp tile 64x32
    const int bx = blockIdx.x;                  // N tile 0..7
    const int by = blockIdx.y;                  // M tile 0..255

    unsigned soff[4], rel[4];
    #pragma unroll
    for (int i = 0; i < 4; i++) {
        unsigned c = tid + i * 256;
        unsigned row = c >> 3, kq = c & 7;
        soff[i] = row * SSTR + kq * 16;
        rel[i]  = row * NXD + kq * 8;
    }
    const char* gA = reinterpret_cast<const char*>(g_A) + (size_t)by * 128 * NXD * 2;
    const char* gB = reinterpret_cast<const char*>(g_B) + (size_t)bx * 128 * NXD * 2;

    auto load_stage = [&](int kt, int s) {
        const uint32_t st = sb + s * STAGE;
        const unsigned kofs = kt * 64;
        #pragma unroll
        for (int i = 0; i < 4; i++) {
            CP16(st + soff[i],          gA + (size_t)(rel[i] + kofs) * 2);
            CP16(st + TILE_B + soff[i], gB + (size_t)(rel[i] + kofs) * 2);
        }
        CP_COMMIT();
    };

    uint32_t abase[4], bbase[2];
    #pragma unroll
    for (int mi = 0; mi < 4; mi++)
        abase[mi] = (wm * 64 + mi * 16 + (l & 15)) * SSTR + (l >> 4) * 16;
    #pragma unroll
    for (int pi = 0; pi < 2; pi++)
        bbase[pi] = (wn * 32 + pi * 16 + (l & 15)) * SSTR + (l >> 4) * 16;

    float acc[4][4][4];
    #pragma unroll
    for (int mi = 0; mi < 4; mi++)
        #pragma unroll
        for (int ni = 0; ni < 4; ni++)
            #pragma unroll
            for (int r = 0; r < 4; r++) acc[mi][ni][r] = 0.0f;

    load_stage(0, 0);

    for (int kt = 0; kt < NKT; kt++) {
        const int s = kt & 1;
        CP_WAIT0();
        __syncthreads();
        if (kt < NKT - 1) load_stage(kt + 1, s ^ 1);

        const uint32_t stA = sb + s * STAGE;
        const uint32_t stB = stA + TILE_B;
        uint32_t h16[4][4][2];                  // fp16 chain accumulators
        #pragma unroll
        for (int ks = 0; ks < 4; ks++) {
            const uint32_t ko = ks * 32;
            uint32_t a_[4][4], b_[2][4];
            #pragma unroll
            for (int mi = 0; mi < 4; mi++) LDSM4(a_[mi], stA + abase[mi] + ko);
            #pragma unroll
            for (int pi = 0; pi < 2; pi++) LDSM4(b_[pi], stB + bbase[pi] + ko);
            #pragma unroll
            for (int mi = 0; mi < 4; mi++)
                #pragma unroll
                for (int ni = 0; ni < 4; ni++) {
                    const int pi = ni >> 1, sel = ni & 1;
                    if (ks == 0) MMAH16_Z(h16[mi][ni], a_[mi], b_[pi][sel], b_[pi][sel + 2]);
                    else         MMAH16_C(h16[mi][ni], a_[mi], b_[pi][sel], b_[pi][sel + 2]);
                }
        }
        // spill fp16 chain -> fp32 accumulators
        #pragma unroll
        for (int mi = 0; mi < 4; mi++)
            #pragma unroll
            for (int ni = 0; ni < 4; ni++) {
                float2 lo = __half22float2(*reinterpret_cast<__half2*>(&h16[mi][ni][0]));
                float2 hi = __half22float2(*reinterpret_cast<__half2*>(&h16[mi][ni][1]));
                acc[mi][ni][0] += lo.x;
                acc[mi][ni][1] += lo.y;
                acc[mi][ni][2] += hi.x;
                acc[mi][ni][3] += hi.y;
            }
        __syncthreads();
    }

    // ================= fused epilogue =================
    const int col0 = bx * 128;
    const int a0   = col0 / H_CNT;
    const int lastc = (col0 + 127 < NC) ? (col0 + 127) : (NC - 1);
    const int a1v  = lastc / H_CNT;

    __half* hst = reinterpret_cast<__half*>(smem);                  // [128][HS] halfs
    float*  W2s = reinterpret_cast<float*>(smem + 128 * HS * 2);

    const int nW = (a1v - a0 + 1) * H_CNT * O_CNT;
    for (int i = tid; i < nW; i += 256)
        W2s[i] = W2[a0 * H_CNT * O_CNT + i];

    #pragma unroll
    for (int mi = 0; mi < 4; mi++) {
        const int lr = wm * 64 + mi * 16 + (l >> 2);
        #pragma unroll
        for (int ni = 0; ni < 4; ni++) {
            const int lc = wn * 32 + ni * 8 + (l & 3) * 2;
            const int gc = col0 + lc;
            float o0 = 0.0f, o1 = 0.0f;
            if (gc < NC) { o0 = g_off[gc]; o1 = g_off[gc + 1]; }
            __half2 v0 = __floats2half2_rn(fmaxf(acc[mi][ni][0] + o0, 0.0f),
                                           fmaxf(acc[mi][ni][1] + o1, 0.0f));
            __half2 v1 = __floats2half2_rn(fmaxf(acc[mi][ni][2] + o0, 0.0f),
                                           fmaxf(acc[mi][ni][3] + o1, 0.0f));
            *reinterpret_cast<__half2*>(hst + lr * HS + lc)       = v0;
            *reinterpret_cast<__half2*>(hst + (lr + 8) * HS + lc) = v1;
        }
    }
    __syncthreads();

    if (tid < 128) {
        const int tok = tid;
        const uint4* hrow4 = reinterpret_cast<const uint4*>(
            reinterpret_cast<const char*>(hst) + tok * (HS * 2));

        float o_loc[12];
        #pragma unroll
        for (int i = 0; i < 12; i++) o_loc[i] = 0.0f;

        const int nu4 = ((lastc + 1) - col0) / 8;
        int hc = col0 - a0 * H_CNT;
        int ai = 0;
        for (int i = 0; i < nu4; i++) {
            const uint4 v = hrow4[i];
            uint32_t pr[4] = {v.x, v.y, v.z, v.w};
            #pragma unroll
            for (int p = 0; p < 4; p++) {
                float2 f = __half22float2(*reinterpret_cast<const __half2*>(&pr[p]));
                const float* wv = &W2s[ai * (H_CNT * O_CNT) + hc * O_CNT];
                o_loc[ai * 3 + 0] += f.x * wv[0] + f.y * wv[3];
                o_loc[ai * 3 + 1] += f.x * wv[1] + f.y * wv[4];
                o_loc[ai * 3 + 2] += f.x * wv[2] + f.y * wv[5];
                hc += 2;
                if (hc == H_CNT) { hc = 0; ai++; }
            }
        }

        const int tg = by * 128 + tok;
        #pragma unroll
        for (int q = 0; q < 4; q++) {
            const int a = a0 + q;
            if (a > a1v) break;
            const int slot = (q == 0 && a0 * H_CNT < col0) ? 1 : 0;
            float* dst = g_obuf[slot] + (size_t)tg * 60 + a * 3;
            dst[0] = o_loc[q * 3 + 0];
            dst[1] = o_loc[q * 3 + 1];
            dst[2] = o_loc[q * 3 + 2];
        }
    }
}

// =====================================================================
// K4: combine slots (slot1 only for chunk-split adapters) + squash
// =====================================================================
__global__ void __launch_bounds__(256) k_sq(const float* __restrict__ b2,
                                            float* __restrict__ out) {
    __shared__ float osm[8][64];
    __shared__ float scl[8][4];
    const int tid = threadIdx.x;
    const int w = tid >> 5, l = tid & 31;
    const int t = blockIdx.x * 8 + w;
    const float* o0 = g_obuf[0] + (size_t)t * 60;
    const float* o1 = g_obuf[1] + (size_t)t * 60;

    #pragma unroll
    for (int r = 0; r < 2; r++) {
        const int p = l + r * 32;
        if (p < A_CNT * O_CNT) {
            const int a = p / 3;
            const int st = a * H_CNT;
            const bool split = (st >> 7) != ((st + H_CNT - 1) >> 7);
            osm[w][p] = o0[p] + (split ? o1[p] : 0.0f) + b2[p];
        }
    }
    __syncwarp();

    if (l < O_CNT) {
        float sq = 0.0f;
        #pragma unroll
        for (int a = 0; a < A_CNT; a++) { float v = osm[w][a * 3 + l]; sq += v * v; }
        scl[w][l] = sqrtf(sq) / (1.0f + sq);
    }
    __syncwarp();

    const int b = t >> 11, sidx = t & (S_LEN - 1);
    #pragma unroll
    for (int r = 0; r < 2; r++) {
        const int p = l + r * 32;
        if (p < A_CNT * O_CNT) {
            const int a = p / 3, j = p - a * 3;
            out[(size_t)(b * A_CNT + a) * (S_LEN * O_CNT) + sidx * 3 + j] =
                osm[w][p] * scl[w][j];
        }
    }
}

// =====================================================================
// launch
// =====================================================================
extern "C" void kernel_launch(void* const* d_in, const int* in_sizes, int n_in,
                              void* d_out, int out_size) {
    (void)in_sizes; (void)n_in; (void)out_size;
    const float* x    = (const float*)d_in[0];
    const float* ln_g = (const float*)d_in[1];
    const float* ln_b = (const float*)d_in[2];
    const float* W1   = (const float*)d_in[3];
    const float* b1   = (const float*)d_in[4];
    const float* W2   = (const float*)d_in[5];
    const float* b2   = (const float*)d_in[6];
    float* out = (float*)d_out;

    cudaFuncSetAttribute(k_gemm, cudaFuncAttributeMaxDynamicSharedMemorySize, SMEMT);

    k_pre<<<NB_PRE, 256>>>(x, ln_g, ln_b, W1);
    k_off2<<<4, 256>>>(b1);
    k_gemm<<<dim3(8, 256), 256, SMEMT>>>(W2);
    k_sq<<<T_TOK / 8, 256>>>(b2, out);
}

// round 15
// speedup vs baseline: 1.0486x; 1.0486x over previous
#include <cuda_runtime.h>
#include <cuda_fp16.h>
#include <cstdint>

// ---------------- problem constants ----------------
#define T_TOK   32768            // B*S tokens
#define NXD     1024             // feature dim (K)
#define A_CNT   20
#define H_CNT   50
#define O_CNT   3
#define NC      1000             // A_CNT*H_CNT real columns
#define NPAD    1024             // padded N
#define S_LEN   2048
#define LN_EPS  1e-5f
#define KB_OFF  8                // k-chunks for k_off partials

// fused-pre grid ranges
#define NB_SPLIT (T_TOK / 8)                 // 4096
#define NB_PREPB NPAD                        // 1024
#define NB_OFF1  (A_CNT * KB_OFF)            // 160
#define NB_PRE   (NB_SPLIT + NB_PREPB + NB_OFF1)

// ---------------- device scratch ----------------
__device__ float g_offp[A_CNT * KB_OFF * H_CNT];             // off partials
__device__ float g_obuf[2][(size_t)T_TOK * 60];              // partial o, 2 slots
__device__ __align__(16) __half g_A[(size_t)T_TOK * NXD];    // 64 MB  xn fp16
__device__ __align__(16) __half g_B[(size_t)NPAD * NXD];     // 2 MB   (ln_g*W1)^T fp16

__device__ __forceinline__ uint32_t s2u(const void* p) {
    uint32_t a;
    asm("{ .reg .u64 t; cvta.to.shared.u64 t, %1; cvt.u32.u64 %0, t; }"
        : "=r"(a) : "l"(p));
    return a;
}
__device__ __forceinline__ unsigned pk2h(__half a, __half b) {
    return (unsigned)__half_as_ushort(a) | ((unsigned)__half_as_ushort(b) << 16);
}

#define CP16(saddr, gaddr) \
    asm volatile("cp.async.cg.shared.global [%0], [%1], 16;" :: "r"(saddr), "l"(gaddr))
#define CP_COMMIT() asm volatile("cp.async.commit_group;" ::: "memory")
#define CP_WAIT0()  asm volatile("cp.async.wait_group 0;" ::: "memory")

#define LDSM4(r, addr) \
    asm volatile("ldmatrix.sync.aligned.m8n8.x4.shared.b16 {%0,%1,%2,%3}, [%4];" \
        : "=r"((r)[0]), "=r"((r)[1]), "=r"((r)[2]), "=r"((r)[3]) : "r"(addr))

#define MMAH(d, a, b0, b1) \
    asm volatile("mma.sync.aligned.m16n8k16.row.col.f32.f16.f16.f32 " \
        "{%0,%1,%2,%3}, {%4,%5,%6,%7}, {%8,%9}, {%0,%1,%2,%3};" \
        : "+f"((d)[0]), "+f"((d)[1]), "+f"((d)[2]), "+f"((d)[3]) \
        : "r"((a)[0]), "r"((a)[1]), "r"((a)[2]), "r"((a)[3]), "r"(b0), "r"(b1))

// =====================================================================
// K1 (fused pre): blockIdx ranges do LN-split | prepB | off1 concurrently
// =====================================================================
__global__ void __launch_bounds__(256) k_pre(const float* __restrict__ x,
                                             const float* __restrict__ ln_g,
                                             const float* __restrict__ ln_b,
                                             const float* __restrict__ W1) {
    const int blk = blockIdx.x;

    if (blk < NB_SPLIT) {
        const int w = threadIdx.x >> 5, l = threadIdx.x & 31;
        const int t = blk * 8 + w;
        const float4* xv = reinterpret_cast<const float4*>(x) + (size_t)t * 256;
        float4 v[8];
        float s = 0.f, q = 0.f;
        #pragma unroll
        for (int j = 0; j < 8; j++) {
            v[j] = xv[l + 32 * j];
            s += v[j].x + v[j].y + v[j].z + v[j].w;
            q += v[j].x * v[j].x + v[j].y * v[j].y + v[j].z * v[j].z + v[j].w * v[j].w;
        }
        #pragma unroll
        for (int o = 16; o > 0; o >>= 1) {
            s += __shfl_xor_sync(0xffffffffu, s, o);
            q += __shfl_xor_sync(0xffffffffu, q, o);
        }
        const float mu  = s * (1.0f / (float)NXD);
        const float var = fmaxf(q * (1.0f / (float)NXD) - mu * mu, 0.0f);
        const float rs  = 1.0f / sqrtf(var + LN_EPS);
        uint2* dst = reinterpret_cast<uint2*>(g_A) + (size_t)t * 256;
        #pragma unroll
        for (int j = 0; j < 8; j++) {
            uint2 H;
            H.x = pk2h(__float2half((v[j].x - mu) * rs), __float2half((v[j].y - mu) * rs));
            H.y = pk2h(__float2half((v[j].z - mu) * rs), __float2half((v[j].w - mu) * rs));
            dst[l + 32 * j] = H;
        }
    } else if (blk < NB_SPLIT + NB_PREPB) {
        const int n = blk - NB_SPLIT;
        int a = 0, h = 0;
        const bool val = (n < NC);
        if (val) { a = n / H_CNT; h = n - a * H_CNT; }
        #pragma unroll
        for (int j = 0; j < 4; j++) {
            const int k = threadIdx.x + j * 256;
            float wv = val ? ln_g[a * NXD + k] * W1[((size_t)a * NXD + k) * H_CNT + h] : 0.0f;
            g_B[(size_t)n * NXD + k] = __float2half(wv);
        }
    } else {
        __shared__ float red[5][H_CNT];
        const int idx = blk - NB_SPLIT - NB_PREPB;
        const int a  = idx / KB_OFF;
        const int kb = idx - a * KB_OFF;
        const int tid = threadIdx.x;
        const int g = tid / H_CNT, h = tid - g * H_CNT;
        float acc = 0.0f;
        if (g < 5) {
            const int n0 = kb * 128;
            for (int r = g; r < 128; r += 5) {
                const int n = n0 + r;
                acc += ln_b[a * NXD + n] * W1[((size_t)a * NXD + n) * H_CNT + h];
            }
            red[g][h] = acc;
        }
        __syncthreads();
        if (tid < H_CNT) {
            float sv = red[0][tid] + red[1][tid] + red[2][tid] + red[3][tid] + red[4][tid];
            g_offp[(a * KB_OFF + kb) * H_CNT + tid] = sv;
        }
    }
}

// =====================================================================
// K3: fp16 mma.sync GEMM (fp32 acc) + fused second-GEMM epilogue
//   CTA 128x128, BK=64, 8 warps (2Mx4N), warp tile 64x32, 2-stage,
//   2 CTAs/SM. Padding-column MMAs predicated off (bx=7).
//   Epilogue computes its own off[] slice from g_offp + b1 (no k_off2).
// =====================================================================
#define SSTR   144
#define TILE_B (128 * SSTR)          // 18432
#define STAGE  (2 * TILE_B)          // 36864
#define SMEMT  (2 * STAGE)           // 73728
#define NKT    16
#define HS     136                   // epilogue h-stage stride (halfs)

__global__ void __launch_bounds__(256, 2) k_gemm(const float* __restrict__ W2,
                                                 const float* __restrict__ b1) {
    extern __shared__ __align__(16) char smem[];
    const uint32_t sb = s2u(smem);
    const int tid = threadIdx.x;
    const int w = tid >> 5, l = tid & 31;
    const int wm = w & 1, wn = w >> 1;          // 2(M) x 4(N), warp tile 64x32
    const int bx = blockIdx.x;                  // N tile 0..7
    const int by = blockIdx.y;                  // M tile 0..255

    unsigned soff[4], rel[4];
    #pragma unroll
    for (int i = 0; i < 4; i++) {
        unsigned c = tid + i * 256;
        unsigned row = c >> 3, kq = c & 7;
        soff[i] = row * SSTR + kq * 16;
        rel[i]  = row * NXD + kq * 8;
    }
    const char* gA = reinterpret_cast<const char*>(g_A) + (size_t)by * 128 * NXD * 2;
    const char* gB = reinterpret_cast<const char*>(g_B) + (size_t)bx * 128 * NXD * 2;

    auto load_stage = [&](int kt, int s) {
        const uint32_t st = sb + s * STAGE;
        const unsigned kofs = kt * 64;
        #pragma unroll
        for (int i = 0; i < 4; i++) {
            CP16(st + soff[i],          gA + (size_t)(rel[i] + kofs) * 2);
            CP16(st + TILE_B + soff[i], gB + (size_t)(rel[i] + kofs) * 2);
        }
        CP_COMMIT();
    };

    uint32_t abase[4], bbase[2];
    #pragma unroll
    for (int mi = 0; mi < 4; mi++)
        abase[mi] = (wm * 64 + mi * 16 + (l & 15)) * SSTR + (l >> 4) * 16;
    #pragma unroll
    for (int pi = 0; pi < 2; pi++)
        bbase[pi] = (wn * 32 + pi * 16 + (l & 15)) * SSTR + (l >> 4) * 16;

    // warp-uniform N-validity of each ni block (false only in bx=7 tail)
    const int col0 = bx * 128;
    bool nvalid[4];
    #pragma unroll
    for (int ni = 0; ni < 4; ni++)
        nvalid[ni] = (col0 + wn * 32 + ni * 8) < NC;

    float acc[4][4][4];
    #pragma unroll
    for (int mi = 0; mi < 4; mi++)
        #pragma unroll
        for (int ni = 0; ni < 4; ni++)
            #pragma unroll
            for (int r = 0; r < 4; r++) acc[mi][ni][r] = 0.0f;

    load_stage(0, 0);

    for (int kt = 0; kt < NKT; kt++) {
        const int s = kt & 1;
        CP_WAIT0();
        __syncthreads();
        if (kt < NKT - 1) load_stage(kt + 1, s ^ 1);

        const uint32_t stA = sb + s * STAGE;
        const uint32_t stB = stA + TILE_B;
        #pragma unroll
        for (int ks = 0; ks < 4; ks++) {
            const uint32_t ko = ks * 32;
            uint32_t a_[4][4], b_[2][4];
            #pragma unroll
            for (int mi = 0; mi < 4; mi++) LDSM4(a_[mi], stA + abase[mi] + ko);
            #pragma unroll
            for (int pi = 0; pi < 2; pi++) LDSM4(b_[pi], stB + bbase[pi] + ko);
            #pragma unroll
            for (int mi = 0; mi < 4; mi++)
                #pragma unroll
                for (int ni = 0; ni < 4; ni++) {
                    const int pi = ni >> 1, sel = ni & 1;
                    if (nvalid[ni])
                        MMAH(acc[mi][ni], a_[mi], b_[pi][sel], b_[pi][sel + 2]);
                }
        }
        __syncthreads();
    }

    // ================= fused epilogue =================
    const int a0   = col0 / H_CNT;
    const int lastc = (col0 + 127 < NC) ? (col0 + 127) : (NC - 1);
    const int a1v  = lastc / H_CNT;

    __half* hst = reinterpret_cast<__half*>(smem);                  // [128][HS] halfs
    float*  W2s  = reinterpret_cast<float*>(smem + 128 * HS * 2);   // <= 600 floats
    float*  offs = reinterpret_cast<float*>(smem + 128 * HS * 2 + 2400); // 128 floats

    // phase 1: W2 slice + per-CTA off slice (from partials + b1)
    const int nW = (a1v - a0 + 1) * H_CNT * O_CNT;
    for (int i = tid; i < nW; i += 256)
        W2s[i] = W2[a0 * H_CNT * O_CNT + i];
    for (int i = tid; i < 128; i += 256) {
        const int gc = col0 + i;
        float sv = 0.0f;
        if (gc < NC) {
            const int a = gc / H_CNT, h = gc - a * H_CNT;
            #pragma unroll
            for (int kb = 0; kb < KB_OFF; kb++)
                sv += g_offp[(a * KB_OFF + kb) * H_CNT + h];
            sv += b1[gc];
        }
        offs[i] = sv;
    }
    __syncthreads();

    // phase 2: stage h = relu(acc + off) as fp16
    #pragma unroll
    for (int mi = 0; mi < 4; mi++) {
        const int lr = wm * 64 + mi * 16 + (l >> 2);
        #pragma unroll
        for (int ni = 0; ni < 4; ni++) {
            const int lc = wn * 32 + ni * 8 + (l & 3) * 2;
            const float o0 = offs[lc], o1 = offs[lc + 1];
            __half2 v0 = __floats2half2_rn(fmaxf(acc[mi][ni][0] + o0, 0.0f),
                                           fmaxf(acc[mi][ni][1] + o1, 0.0f));
            __half2 v1 = __floats2half2_rn(fmaxf(acc[mi][ni][2] + o0, 0.0f),
                                           fmaxf(acc[mi][ni][3] + o1, 0.0f));
            *reinterpret_cast<__half2*>(hst + lr * HS + lc)       = v0;
            *reinterpret_cast<__half2*>(hst + (lr + 8) * HS + lc) = v1;
        }
    }
    __syncthreads();

    // phase 3: per-thread token GEMV (threads 0..127), streamed uint4
    if (tid < 128) {
        const int tok = tid;
        const uint4* hrow4 = reinterpret_cast<const uint4*>(
            reinterpret_cast<const char*>(hst) + tok * (HS * 2));

        float o_loc[12];
        #pragma unroll
        for (int i = 0; i < 12; i++) o_loc[i] = 0.0f;

        const int nu4 = ((lastc + 1) - col0) / 8;
        int hc = col0 - a0 * H_CNT;
        int ai = 0;
        for (int i = 0; i < nu4; i++) {
            const uint4 v = hrow4[i];
            uint32_t pr[4] = {v.x, v.y, v.z, v.w};
            #pragma unroll
            for (int p = 0; p < 4; p++) {
                float2 f = __half22float2(*reinterpret_cast<const __half2*>(&pr[p]));
                const float* wv = &W2s[ai * (H_CNT * O_CNT) + hc * O_CNT];
                o_loc[ai * 3 + 0] += f.x * wv[0] + f.y * wv[3];
                o_loc[ai * 3 + 1] += f.x * wv[1] + f.y * wv[4];
                o_loc[ai * 3 + 2] += f.x * wv[2] + f.y * wv[5];
                hc += 2;
                if (hc == H_CNT) { hc = 0; ai++; }
            }
        }

        const int tg = by * 128 + tok;
        #pragma unroll
        for (int q = 0; q < 4; q++) {
            const int a = a0 + q;
            if (a > a1v) break;
            const int slot = (q == 0 && a0 * H_CNT < col0) ? 1 : 0;
            float* dst = g_obuf[slot] + (size_t)tg * 60 + a * 3;
            dst[0] = o_loc[q * 3 + 0];
            dst[1] = o_loc[q * 3 + 1];
            dst[2] = o_loc[q * 3 + 2];
        }
    }
}

// =====================================================================
// K4: combine slots (slot1 only for chunk-split adapters) + squash
// =====================================================================
__global__ void __launch_bounds__(256) k_sq(const float* __restrict__ b2,
                                            float* __restrict__ out) {
    __shared__ float osm[8][64];
    __shared__ float scl[8][4];
    const int tid = threadIdx.x;
    const int w = tid >> 5, l = tid & 31;
    const int t = blockIdx.x * 8 + w;
    const float* o0 = g_obuf[0] + (size_t)t * 60;
    const float* o1 = g_obuf[1] + (size_t)t * 60;

    #pragma unroll
    for (int r = 0; r < 2; r++) {
        const int p = l + r * 32;
        if (p < A_CNT * O_CNT) {
            const int a = p / 3;
            const int st = a * H_CNT;
            const bool split = (st >> 7) != ((st + H_CNT - 1) >> 7);
            osm[w][p] = o0[p] + (split ? o1[p] : 0.0f) + b2[p];
        }
    }
    __syncwarp();

    if (l < O_CNT) {
        float sq = 0.0f;
        #pragma unroll
        for (int a = 0; a < A_CNT; a++) { float v = osm[w][a * 3 + l]; sq += v * v; }
        scl[w][l] = sqrtf(sq) / (1.0f + sq);
    }
    __syncwarp();

    const int b = t >> 11, sidx = t & (S_LEN - 1);
    #pragma unroll
    for (int r = 0; r < 2; r++) {
        const int p = l + r * 32;
        if (p < A_CNT * O_CNT) {
            const int a = p / 3, j = p - a * 3;
            out[(size_t)(b * A_CNT + a) * (S_LEN * O_CNT) + sidx * 3 + j] =
                osm[w][p] * scl[w][j];
        }
    }
}

// =====================================================================
// launch
// =====================================================================
extern "C" void kernel_launch(void* const* d_in, const int* in_sizes, int n_in,
                              void* d_out, int out_size) {
    (void)in_sizes; (void)n_in; (void)out_size;
    const float* x    = (const float*)d_in[0];
    const float* ln_g = (const float*)d_in[1];
    const float* ln_b = (const float*)d_in[2];
    const float* W1   = (const float*)d_in[3];
    const float* b1   = (const float*)d_in[4];
    const float* W2   = (const float*)d_in[5];
    const float* b2   = (const float*)d_in[6];
    float* out = (float*)d_out;

    cudaFuncSetAttribute(k_gemm, cudaFuncAttributeMaxDynamicSharedMemorySize, SMEMT);

    k_pre<<<NB_PRE, 256>>>(x, ln_g, ln_b, W1);
    k_gemm<<<dim3(8, 256), 256, SMEMT>>>(W2, b1);
    k_sq<<<T_TOK / 8, 256>>>(b2, out);
}

// round 16
// speedup vs baseline: 1.0700x; 1.0204x over previous
#include <cuda_runtime.h>
#include <cuda_fp16.h>
#include <cstdint>

// ---------------- problem constants ----------------
#define T_TOK   32768            // B*S tokens
#define NXD     1024             // feature dim (K)
#define A_CNT   20
#define H_CNT   50
#define O_CNT   3
#define NC      1000             // A_CNT*H_CNT real columns
#define NPAD    1024             // padded N
#define S_LEN   2048
#define LN_EPS  1e-5f
#define KB_OFF  8                // k-chunks for k_off partials

// fused-pre grid ranges
#define NB_SPLIT (T_TOK / 8)                 // 4096
#define NB_PREPB NPAD                        // 1024
#define NB_OFF1  (A_CNT * KB_OFF)            // 160
#define NB_PRE   (NB_SPLIT + NB_PREPB + NB_OFF1)

// ---------------- device scratch ----------------
__device__ float g_off[NC];
__device__ float g_offp[A_CNT * KB_OFF * H_CNT];             // off partials
__device__ float g_obuf[2][(size_t)T_TOK * 60];              // partial o, 2 slots
__device__ __align__(16) __half g_A[(size_t)T_TOK * NXD];    // 64 MB  xn fp16
__device__ __align__(16) __half g_B[(size_t)NPAD * NXD];     // 2 MB   (ln_g*W1)^T fp16

__device__ __forceinline__ uint32_t s2u(const void* p) {
    uint32_t a;
    asm("{ .reg .u64 t; cvta.to.shared.u64 t, %1; cvt.u32.u64 %0, t; }"
        : "=r"(a) : "l"(p));
    return a;
}
__device__ __forceinline__ unsigned pk2h(__half a, __half b) {
    return (unsigned)__half_as_ushort(a) | ((unsigned)__half_as_ushort(b) << 16);
}

#define CP16(saddr, gaddr) \
    asm volatile("cp.async.cg.shared.global [%0], [%1], 16;" :: "r"(saddr), "l"(gaddr))
#define CP_COMMIT() asm volatile("cp.async.commit_group;" ::: "memory")
#define CP_WAIT0()  asm volatile("cp.async.wait_group 0;" ::: "memory")

#define LDSM4(r, addr) \
    asm volatile("ldmatrix.sync.aligned.m8n8.x4.shared.b16 {%0,%1,%2,%3}, [%4];" \
        : "=r"((r)[0]), "=r"((r)[1]), "=r"((r)[2]), "=r"((r)[3]) : "r"(addr))

#define MMAH(d, a, b0, b1) \
    asm volatile("mma.sync.aligned.m16n8k16.row.col.f32.f16.f16.f32 " \
        "{%0,%1,%2,%3}, {%4,%5,%6,%7}, {%8,%9}, {%0,%1,%2,%3};" \
        : "+f"((d)[0]), "+f"((d)[1]), "+f"((d)[2]), "+f"((d)[3]) \
        : "r"((a)[0]), "r"((a)[1]), "r"((a)[2]), "r"((a)[3]), "r"(b0), "r"(b1))

// =====================================================================
// K1 (fused pre): blockIdx ranges do LN-split | prepB | off1 concurrently
// =====================================================================
__global__ void __launch_bounds__(256) k_pre(const float* __restrict__ x,
                                             const float* __restrict__ ln_g,
                                             const float* __restrict__ ln_b,
                                             const float* __restrict__ W1) {
    const int blk = blockIdx.x;

    if (blk < NB_SPLIT) {
        const int w = threadIdx.x >> 5, l = threadIdx.x & 31;
        const int t = blk * 8 + w;
        const float4* xv = reinterpret_cast<const float4*>(x) + (size_t)t * 256;
        float4 v[8];
        float s = 0.f, q = 0.f;
        #pragma unroll
        for (int j = 0; j < 8; j++) {
            v[j] = xv[l + 32 * j];
            s += v[j].x + v[j].y + v[j].z + v[j].w;
            q += v[j].x * v[j].x + v[j].y * v[j].y + v[j].z * v[j].z + v[j].w * v[j].w;
        }
        #pragma unroll
        for (int o = 16; o > 0; o >>= 1) {
            s += __shfl_xor_sync(0xffffffffu, s, o);
            q += __shfl_xor_sync(0xffffffffu, q, o);
        }
        const float mu  = s * (1.0f / (float)NXD);
        const float var = fmaxf(q * (1.0f / (float)NXD) - mu * mu, 0.0f);
        const float rs  = 1.0f / sqrtf(var + LN_EPS);
        uint2* dst = reinterpret_cast<uint2*>(g_A) + (size_t)t * 256;
        #pragma unroll
        for (int j = 0; j < 8; j++) {
            uint2 H;
            H.x = pk2h(__float2half((v[j].x - mu) * rs), __float2half((v[j].y - mu) * rs));
            H.y = pk2h(__float2half((v[j].z - mu) * rs), __float2half((v[j].w - mu) * rs));
            dst[l + 32 * j] = H;
        }
    } else if (blk < NB_SPLIT + NB_PREPB) {
        const int n = blk - NB_SPLIT;
        int a = 0, h = 0;
        const bool val = (n < NC);
        if (val) { a = n / H_CNT; h = n - a * H_CNT; }
        #pragma unroll
        for (int j = 0; j < 4; j++) {
            const int k = threadIdx.x + j * 256;
            float wv = val ? ln_g[a * NXD + k] * W1[((size_t)a * NXD + k) * H_CNT + h] : 0.0f;
            g_B[(size_t)n * NXD + k] = __float2half(wv);
        }
    } else {
        __shared__ float red[5][H_CNT];
        const int idx = blk - NB_SPLIT - NB_PREPB;
        const int a  = idx / KB_OFF;
        const int kb = idx - a * KB_OFF;
        const int tid = threadIdx.x;
        const int g = tid / H_CNT, h = tid - g * H_CNT;
        float acc = 0.0f;
        if (g < 5) {
            const int n0 = kb * 128;
            for (int r = g; r < 128; r += 5) {
                const int n = n0 + r;
                acc += ln_b[a * NXD + n] * W1[((size_t)a * NXD + n) * H_CNT + h];
            }
            red[g][h] = acc;
        }
        __syncthreads();
        if (tid < H_CNT) {
            float sv = red[0][tid] + red[1][tid] + red[2][tid] + red[3][tid] + red[4][tid];
            g_offp[(a * KB_OFF + kb) * H_CNT + tid] = sv;
        }
    }
}

// =====================================================================
// K2: reduce off partials + b1 -> g_off
// =====================================================================
__global__ void __launch_bounds__(256) k_off2(const float* __restrict__ b1) {
    const int p = blockIdx.x * 256 + threadIdx.x;
    if (p >= NC) return;
    const int a = p / H_CNT, h = p - a * H_CNT;
    float s = 0.0f;
    #pragma unroll
    for (int kb = 0; kb < KB_OFF; kb++)
        s += g_offp[(a * KB_OFF + kb) * H_CNT + h];
    g_off[p] = s + b1[p];
}

// =====================================================================
// K3: fp16 mma.sync GEMM (fp32 acc, R13 mainloop) + fused epilogue
//   CTA 128x128, BK=64, 8 warps (2Mx4N), warp tile 64x32, 2-stage,
//   2 CTAs/SM. NO MMA predication (R15 showed it regresses).
//   Epilogue GEMV now split 2 threads/token (half-chunk each) + combine.
// =====================================================================
#define SSTR   144
#define TILE_B (128 * SSTR)          // 18432
#define STAGE  (2 * TILE_B)          // 36864
#define SMEMT  (2 * STAGE)           // 73728
#define NKT    16
#define HS     136                   // epilogue h-stage stride (halfs)

__global__ void __launch_bounds__(256, 2) k_gemm(const float* __restrict__ W2) {
    extern __shared__ __align__(16) char smem[];
    const uint32_t sb = s2u(smem);
    const int tid = threadIdx.x;
    const int w = tid >> 5, l = tid & 31;
    const int wm = w & 1, wn = w >> 1;          // 2(M) x 4(N), warp tile 64x32
    const int bx = blockIdx.x;                  // N tile 0..7
    const int by = blockIdx.y;                  // M tile 0..255

    unsigned soff[4], rel[4];
    #pragma unroll
    for (int i = 0; i < 4; i++) {
        unsigned c = tid + i * 256;
        unsigned row = c >> 3, kq = c & 7;
        soff[i] = row * SSTR + kq * 16;
        rel[i]  = row * NXD + kq * 8;
    }
    const char* gA = reinterpret_cast<const char*>(g_A) + (size_t)by * 128 * NXD * 2;
    const char* gB = reinterpret_cast<const char*>(g_B) + (size_t)bx * 128 * NXD * 2;

    auto load_stage = [&](int kt, int s) {
        const uint32_t st = sb + s * STAGE;
        const unsigned kofs = kt * 64;
        #pragma unroll
        for (int i = 0; i < 4; i++) {
            CP16(st + soff[i],          gA + (size_t)(rel[i] + kofs) * 2);
            CP16(st + TILE_B + soff[i], gB + (size_t)(rel[i] + kofs) * 2);
        }
        CP_COMMIT();
    };

    uint32_t abase[4], bbase[2];
    #pragma unroll
    for (int mi = 0; mi < 4; mi++)
        abase[mi] = (wm * 64 + mi * 16 + (l & 15)) * SSTR + (l >> 4) * 16;
    #pragma unroll
    for (int pi = 0; pi < 2; pi++)
        bbase[pi] = (wn * 32 + pi * 16 + (l & 15)) * SSTR + (l >> 4) * 16;

    float acc[4][4][4];
    #pragma unroll
    for (int mi = 0; mi < 4; mi++)
        #pragma unroll
        for (int ni = 0; ni < 4; ni++)
            #pragma unroll
            for (int r = 0; r < 4; r++) acc[mi][ni][r] = 0.0f;

    load_stage(0, 0);

    for (int kt = 0; kt < NKT; kt++) {
        const int s = kt & 1;
        CP_WAIT0();
        __syncthreads();
        if (kt < NKT - 1) load_stage(kt + 1, s ^ 1);

        const uint32_t stA = sb + s * STAGE;
        const uint32_t stB = stA + TILE_B;
        #pragma unroll
        for (int ks = 0; ks < 4; ks++) {
            const uint32_t ko = ks * 32;
            uint32_t a_[4][4], b_[2][4];
            #pragma unroll
            for (int mi = 0; mi < 4; mi++) LDSM4(a_[mi], stA + abase[mi] + ko);
            #pragma unroll
            for (int pi = 0; pi < 2; pi++) LDSM4(b_[pi], stB + bbase[pi] + ko);
            #pragma unroll
            for (int mi = 0; mi < 4; mi++)
                #pragma unroll
                for (int ni = 0; ni < 4; ni++) {
                    const int pi = ni >> 1, sel = ni & 1;
                    MMAH(acc[mi][ni], a_[mi], b_[pi][sel], b_[pi][sel + 2]);
                }
        }
        __syncthreads();
    }

    // ================= fused epilogue =================
    const int col0 = bx * 128;
    const int a0   = col0 / H_CNT;
    const int lastc = (col0 + 127 < NC) ? (col0 + 127) : (NC - 1);
    const int a1v  = lastc / H_CNT;

    __half* hst  = reinterpret_cast<__half*>(smem);                 // [128][HS] 34816 B
    float*  W2s  = reinterpret_cast<float*>(smem + 34816);          // 2400 B
    float*  o_sm = reinterpret_cast<float*>(smem + 34816 + 2432);   // [2][128][12] 12288 B

    // phase 1: W2 slice
    const int nW = (a1v - a0 + 1) * H_CNT * O_CNT;
    for (int i = tid; i < nW; i += 256)
        W2s[i] = W2[a0 * H_CNT * O_CNT + i];

    // phase 2: stage h = relu(acc + off) as fp16
    #pragma unroll
    for (int mi = 0; mi < 4; mi++) {
        const int lr = wm * 64 + mi * 16 + (l >> 2);
        #pragma unroll
        for (int ni = 0; ni < 4; ni++) {
            const int lc = wn * 32 + ni * 8 + (l & 3) * 2;
            const int gc = col0 + lc;
            float o0 = 0.0f, o1 = 0.0f;
            if (gc < NC) { o0 = g_off[gc]; o1 = g_off[gc + 1]; }
            __half2 v0 = __floats2half2_rn(fmaxf(acc[mi][ni][0] + o0, 0.0f),
                                           fmaxf(acc[mi][ni][1] + o1, 0.0f));
            __half2 v1 = __floats2half2_rn(fmaxf(acc[mi][ni][2] + o0, 0.0f),
                                           fmaxf(acc[mi][ni][3] + o1, 0.0f));
            *reinterpret_cast<__half2*>(hst + lr * HS + lc)       = v0;
            *reinterpret_cast<__half2*>(hst + (lr + 8) * HS + lc) = v1;
        }
    }
    __syncthreads();

    // phase 3: GEMV, 2 threads per token (64 cols each), partials to smem
    {
        const int half = tid >> 7;              // 0 or 1
        const int tok  = tid & 127;
        const int cb   = col0 + half * 64;      // this thread's first col
        const int cend = lastc + 1;

        float o_loc[12];
        #pragma unroll
        for (int i = 0; i < 12; i++) o_loc[i] = 0.0f;

        if (cb < cend) {
            const int ncols = ((cend - cb) < 64) ? (cend - cb) : 64;  // 64, or 40 (bx=7 half1)
            const int nu4 = ncols / 8;
            const uint4* hrow4 = reinterpret_cast<const uint4*>(
                reinterpret_cast<const char*>(hst) + tok * (HS * 2)) + half * 8;
            const int aa = cb / H_CNT;
            int hc = cb - aa * H_CNT;            // even (cb multiple of 64, H=50 -> even)
            int ai = aa - a0;                    // chunk-local adapter slot
            for (int i = 0; i < nu4; i++) {
                const uint4 v = hrow4[i];
                uint32_t pr[4] = {v.x, v.y, v.z, v.w};
                #pragma unroll
                for (int p = 0; p < 4; p++) {
                    float2 f = __half22float2(*reinterpret_cast<const __half2*>(&pr[p]));
                    const float* wv = &W2s[ai * (H_CNT * O_CNT) + hc * O_CNT];
                    o_loc[ai * 3 + 0] += f.x * wv[0] + f.y * wv[3];
                    o_loc[ai * 3 + 1] += f.x * wv[1] + f.y * wv[4];
                    o_loc[ai * 3 + 2] += f.x * wv[2] + f.y * wv[5];
                    hc += 2;
                    if (hc == H_CNT) { hc = 0; ai++; }
                }
            }
        }
        float* dst = o_sm + (half * 128 + tok) * 12;
        #pragma unroll
        for (int i = 0; i < 12; i++) dst[i] = o_loc[i];
    }
    __syncthreads();

    // phase 4: combine halves, store partial o to g_obuf slots
    if (tid < 128) {
        const int tok = tid;
        const float* s0 = o_sm + tok * 12;
        const float* s1 = o_sm + (128 + tok) * 12;
        const int tg = by * 128 + tok;
        #pragma unroll
        for (int q = 0; q < 4; q++) {
            const int a = a0 + q;
            if (a > a1v) break;
            const int slot = (q == 0 && a0 * H_CNT < col0) ? 1 : 0;
            float* dst = g_obuf[slot] + (size_t)tg * 60 + a * 3;
            dst[0] = s0[q * 3 + 0] + s1[q * 3 + 0];
            dst[1] = s0[q * 3 + 1] + s1[q * 3 + 1];
            dst[2] = s0[q * 3 + 2] + s1[q * 3 + 2];
        }
    }
}

// =====================================================================
// K4: combine slots (slot1 only for chunk-split adapters) + squash
// =====================================================================
__global__ void __launch_bounds__(256) k_sq(const float* __restrict__ b2,
                                            float* __restrict__ out) {
    __shared__ float osm[8][64];
    __shared__ float scl[8][4];
    const int tid = threadIdx.x;
    const int w = tid >> 5, l = tid & 31;
    const int t = blockIdx.x * 8 + w;
    const float* o0 = g_obuf[0] + (size_t)t * 60;
    const float* o1 = g_obuf[1] + (size_t)t * 60;

    #pragma unroll
    for (int r = 0; r < 2; r++) {
        const int p = l + r * 32;
        if (p < A_CNT * O_CNT) {
            const int a = p / 3;
            const int st = a * H_CNT;
            const bool split = (st >> 7) != ((st + H_CNT - 1) >> 7);
            osm[w][p] = o0[p] + (split ? o1[p] : 0.0f) + b2[p];
        }
    }
    __syncwarp();

    if (l < O_CNT) {
        float sq = 0.0f;
        #pragma unroll
        for (int a = 0; a < A_CNT; a++) { float v = osm[w][a * 3 + l]; sq += v * v; }
        scl[w][l] = sqrtf(sq) / (1.0f + sq);
    }
    __syncwarp();

    const int b = t >> 11, sidx = t & (S_LEN - 1);
    #pragma unroll
    for (int r = 0; r < 2; r++) {
        const int p = l + r * 32;
        if (p < A_CNT * O_CNT) {
            const int a = p / 3, j = p - a * 3;
            out[(size_t)(b * A_CNT + a) * (S_LEN * O_CNT) + sidx * 3 + j] =
                osm[w][p] * scl[w][j];
        }
    }
}

// =====================================================================
// launch
// =====================================================================
extern "C" void kernel_launch(void* const* d_in, const int* in_sizes, int n_in,
                              void* d_out, int out_size) {
    (void)in_sizes; (void)n_in; (void)out_size;
    const float* x    = (const float*)d_in[0];
    const float* ln_g = (const float*)d_in[1];
    const float* ln_b = (const float*)d_in[2];
    const float* W1   = (const float*)d_in[3];
    const float* b1   = (const float*)d_in[4];
    const float* W2   = (const float*)d_in[5];
    const float* b2   = (const float*)d_in[6];
    float* out = (float*)d_out;

    cudaFuncSetAttribute(k_gemm, cudaFuncAttributeMaxDynamicSharedMemorySize, SMEMT);

    k_pre<<<NB_PRE, 256>>>(x, ln_g, ln_b, W1);
    k_off2<<<4, 256>>>(b1);
    k_gemm<<<dim3(8, 256), 256, SMEMT>>>(W2);
    k_sq<<<T_TOK / 8, 256>>>(b2, out);
}

// round 17
// speedup vs baseline: 1.0890x; 1.0178x over previous
#include <cuda_runtime.h>
#include <cuda_fp16.h>
#include <cstdint>

// ---------------- problem constants ----------------
#define T_TOK   32768            // B*S tokens
#define NXD     1024             // feature dim (K)
#define A_CNT   20
#define H_CNT   50
#define O_CNT   3
#define NC      1000             // A_CNT*H_CNT real columns
#define NPAD    1024             // padded N
#define S_LEN   2048
#define LN_EPS  1e-5f
#define KB_OFF  8                // k-chunks for k_off partials

// fused-pre grid ranges
#define NB_SPLIT (T_TOK / 8)                 // 4096
#define NB_PREPB NPAD                        // 1024
#define NB_OFF1  (A_CNT * KB_OFF)            // 160
#define NB_PRE   (NB_SPLIT + NB_PREPB + NB_OFF1)

// ---------------- device scratch ----------------
__device__ float g_off[NC];
__device__ float g_offp[A_CNT * KB_OFF * H_CNT];             // off partials
__device__ float g_obuf[2][(size_t)T_TOK * 60];              // partial o, 2 slots
__device__ __align__(16) __half g_A[(size_t)T_TOK * NXD];    // 64 MB  xn fp16
__device__ __align__(16) __half g_B[(size_t)NPAD * NXD];     // 2 MB   (ln_g*W1)^T fp16

__device__ __forceinline__ uint32_t s2u(const void* p) {
    uint32_t a;
    asm("{ .reg .u64 t; cvta.to.shared.u64 t, %1; cvt.u32.u64 %0, t; }"
        : "=r"(a) : "l"(p));
    return a;
}
__device__ __forceinline__ unsigned pk2h(__half a, __half b) {
    return (unsigned)__half_as_ushort(a) | ((unsigned)__half_as_ushort(b) << 16);
}

#define CP16(saddr, gaddr) \
    asm volatile("cp.async.cg.shared.global [%0], [%1], 16;" :: "r"(saddr), "l"(gaddr))
#define CP_COMMIT() asm volatile("cp.async.commit_group;" ::: "memory")
#define CP_WAIT0()  asm volatile("cp.async.wait_group 0;" ::: "memory")

#define LDSM4(r, addr) \
    asm volatile("ldmatrix.sync.aligned.m8n8.x4.shared.b16 {%0,%1,%2,%3}, [%4];" \
        : "=r"((r)[0]), "=r"((r)[1]), "=r"((r)[2]), "=r"((r)[3]) : "r"(addr))

#define MMAH(d, a, b0, b1) \
    asm volatile("mma.sync.aligned.m16n8k16.row.col.f32.f16.f16.f32 " \
        "{%0,%1,%2,%3}, {%4,%5,%6,%7}, {%8,%9}, {%0,%1,%2,%3};" \
        : "+f"((d)[0]), "+f"((d)[1]), "+f"((d)[2]), "+f"((d)[3]) \
        : "r"((a)[0]), "r"((a)[1]), "r"((a)[2]), "r"((a)[3]), "r"(b0), "r"(b1))

// =====================================================================
// K1 (fused pre): blockIdx ranges do LN-split | prepB | off1 concurrently
// =====================================================================
__global__ void __launch_bounds__(256) k_pre(const float* __restrict__ x,
                                             const float* __restrict__ ln_g,
                                             const float* __restrict__ ln_b,
                                             const float* __restrict__ W1) {
    const int blk = blockIdx.x;

    if (blk < NB_SPLIT) {
        const int w = threadIdx.x >> 5, l = threadIdx.x & 31;
        const int t = blk * 8 + w;
        const float4* xv = reinterpret_cast<const float4*>(x) + (size_t)t * 256;
        float4 v[8];
        float s = 0.f, q = 0.f;
        #pragma unroll
        for (int j = 0; j < 8; j++) {
            v[j] = xv[l + 32 * j];
            s += v[j].x + v[j].y + v[j].z + v[j].w;
            q += v[j].x * v[j].x + v[j].y * v[j].y + v[j].z * v[j].z + v[j].w * v[j].w;
        }
        #pragma unroll
        for (int o = 16; o > 0; o >>= 1) {
            s += __shfl_xor_sync(0xffffffffu, s, o);
            q += __shfl_xor_sync(0xffffffffu, q, o);
        }
        const float mu  = s * (1.0f / (float)NXD);
        const float var = fmaxf(q * (1.0f / (float)NXD) - mu * mu, 0.0f);
        const float rs  = 1.0f / sqrtf(var + LN_EPS);
        uint2* dst = reinterpret_cast<uint2*>(g_A) + (size_t)t * 256;
        #pragma unroll
        for (int j = 0; j < 8; j++) {
            uint2 H;
            H.x = pk2h(__float2half((v[j].x - mu) * rs), __float2half((v[j].y - mu) * rs));
            H.y = pk2h(__float2half((v[j].z - mu) * rs), __float2half((v[j].w - mu) * rs));
            dst[l + 32 * j] = H;
        }
    } else if (blk < NB_SPLIT + NB_PREPB) {
        const int n = blk - NB_SPLIT;
        int a = 0, h = 0;
        const bool val = (n < NC);
        if (val) { a = n / H_CNT; h = n - a * H_CNT; }
        #pragma unroll
        for (int j = 0; j < 4; j++) {
            const int k = threadIdx.x + j * 256;
            float wv = val ? ln_g[a * NXD + k] * W1[((size_t)a * NXD + k) * H_CNT + h] : 0.0f;
            g_B[(size_t)n * NXD + k] = __float2half(wv);
        }
    } else {
        __shared__ float red[5][H_CNT];
        const int idx = blk - NB_SPLIT - NB_PREPB;
        const int a  = idx / KB_OFF;
        const int kb = idx - a * KB_OFF;
        const int tid = threadIdx.x;
        const int g = tid / H_CNT, h = tid - g * H_CNT;
        float acc = 0.0f;
        if (g < 5) {
            const int n0 = kb * 128;
            for (int r = g; r < 128; r += 5) {
                const int n = n0 + r;
                acc += ln_b[a * NXD + n] * W1[((size_t)a * NXD + n) * H_CNT + h];
            }
            red[g][h] = acc;
        }
        __syncthreads();
        if (tid < H_CNT) {
            float sv = red[0][tid] + red[1][tid] + red[2][tid] + red[3][tid] + red[4][tid];
            g_offp[(a * KB_OFF + kb) * H_CNT + tid] = sv;
        }
    }
}

// =====================================================================
// K2: reduce off partials + b1 -> g_off
// =====================================================================
__global__ void __launch_bounds__(256) k_off2(const float* __restrict__ b1) {
    const int p = blockIdx.x * 256 + threadIdx.x;
    if (p >= NC) return;
    const int a = p / H_CNT, h = p - a * H_CNT;
    float s = 0.0f;
    #pragma unroll
    for (int kb = 0; kb < KB_OFF; kb++)
        s += g_offp[(a * KB_OFF + kb) * H_CNT + h];
    g_off[p] = s + b1[p];
}

// =====================================================================
// K3: fp16 mma.sync GEMM (fp32 acc, R13 mainloop minus redundant barrier)
//   CTA 128x128, BK=64, 8 warps (2Mx4N), warp tile 64x32, 2-stage,
//   2 CTAs/SM. Epilogue: R13 128-thread GEMV (best measured).
//   Mainloop has ONE barrier per kt: top-of-loop sync already orders
//   "all warps done reading stage s" before load_stage(kt+2, s).
// =====================================================================
#define SSTR   144
#define TILE_B (128 * SSTR)          // 18432
#define STAGE  (2 * TILE_B)          // 36864
#define SMEMT  (2 * STAGE)           // 73728
#define NKT    16
#define HS     136                   // epilogue h-stage stride (halfs)

__global__ void __launch_bounds__(256, 2) k_gemm(const float* __restrict__ W2) {
    extern __shared__ __align__(16) char smem[];
    const uint32_t sb = s2u(smem);
    const int tid = threadIdx.x;
    const int w = tid >> 5, l = tid & 31;
    const int wm = w & 1, wn = w >> 1;          // 2(M) x 4(N), warp tile 64x32
    const int bx = blockIdx.x;                  // N tile 0..7
    const int by = blockIdx.y;                  // M tile 0..255

    unsigned soff[4], rel[4];
    #pragma unroll
    for (int i = 0; i < 4; i++) {
        unsigned c = tid + i * 256;
        unsigned row = c >> 3, kq = c & 7;
        soff[i] = row * SSTR + kq * 16;
        rel[i]  = row * NXD + kq * 8;
    }
    const char* gA = reinterpret_cast<const char*>(g_A) + (size_t)by * 128 * NXD * 2;
    const char* gB = reinterpret_cast<const char*>(g_B) + (size_t)bx * 128 * NXD * 2;

    auto load_stage = [&](int kt, int s) {
        const uint32_t st = sb + s * STAGE;
        const unsigned kofs = kt * 64;
        #pragma unroll
        for (int i = 0; i < 4; i++) {
            CP16(st + soff[i],          gA + (size_t)(rel[i] + kofs) * 2);
            CP16(st + TILE_B + soff[i], gB + (size_t)(rel[i] + kofs) * 2);
        }
        CP_COMMIT();
    };

    uint32_t abase[4], bbase[2];
    #pragma unroll
    for (int mi = 0; mi < 4; mi++)
        abase[mi] = (wm * 64 + mi * 16 + (l & 15)) * SSTR + (l >> 4) * 16;
    #pragma unroll
    for (int pi = 0; pi < 2; pi++)
        bbase[pi] = (wn * 32 + pi * 16 + (l & 15)) * SSTR + (l >> 4) * 16;

    float acc[4][4][4];
    #pragma unroll
    for (int mi = 0; mi < 4; mi++)
        #pragma unroll
        for (int ni = 0; ni < 4; ni++)
            #pragma unroll
            for (int r = 0; r < 4; r++) acc[mi][ni][r] = 0.0f;

    load_stage(0, 0);

    for (int kt = 0; kt < NKT; kt++) {
        const int s = kt & 1;
        CP_WAIT0();
        __syncthreads();    // stage(kt) visible; all warps done reading stage s from kt-2
        if (kt < NKT - 1) load_stage(kt + 1, s ^ 1);

        const uint32_t stA = sb + s * STAGE;
        const uint32_t stB = stA + TILE_B;
        #pragma unroll
        for (int ks = 0; ks < 4; ks++) {
            const uint32_t ko = ks * 32;
            uint32_t a_[4][4], b_[2][4];
            #pragma unroll
            for (int mi = 0; mi < 4; mi++) LDSM4(a_[mi], stA + abase[mi] + ko);
            #pragma unroll
            for (int pi = 0; pi < 2; pi++) LDSM4(b_[pi], stB + bbase[pi] + ko);
            #pragma unroll
            for (int mi = 0; mi < 4; mi++)
                #pragma unroll
                for (int ni = 0; ni < 4; ni++) {
                    const int pi = ni >> 1, sel = ni & 1;
                    MMAH(acc[mi][ni], a_[mi], b_[pi][sel], b_[pi][sel + 2]);
                }
        }
        // no trailing barrier: next iteration's top barrier provides the ordering
    }
    __syncthreads();   // before smem reuse in epilogue

    // ================= fused epilogue (R13 form) =================
    const int col0 = bx * 128;
    const int a0   = col0 / H_CNT;
    const int lastc = (col0 + 127 < NC) ? (col0 + 127) : (NC - 1);
    const int a1v  = lastc / H_CNT;

    __half* hst = reinterpret_cast<__half*>(smem);                  // [128][HS] halfs
    float*  W2s = reinterpret_cast<float*>(smem + 128 * HS * 2);

    const int nW = (a1v - a0 + 1) * H_CNT * O_CNT;
    for (int i = tid; i < nW; i += 256)
        W2s[i] = W2[a0 * H_CNT * O_CNT + i];

    #pragma unroll
    for (int mi = 0; mi < 4; mi++) {
        const int lr = wm * 64 + mi * 16 + (l >> 2);
        #pragma unroll
        for (int ni = 0; ni < 4; ni++) {
            const int lc = wn * 32 + ni * 8 + (l & 3) * 2;
            const int gc = col0 + lc;
            float o0 = 0.0f, o1 = 0.0f;
            if (gc < NC) { o0 = g_off[gc]; o1 = g_off[gc + 1]; }
            __half2 v0 = __floats2half2_rn(fmaxf(acc[mi][ni][0] + o0, 0.0f),
                                           fmaxf(acc[mi][ni][1] + o1, 0.0f));
            __half2 v1 = __floats2half2_rn(fmaxf(acc[mi][ni][2] + o0, 0.0f),
                                           fmaxf(acc[mi][ni][3] + o1, 0.0f));
            *reinterpret_cast<__half2*>(hst + lr * HS + lc)       = v0;
            *reinterpret_cast<__half2*>(hst + (lr + 8) * HS + lc) = v1;
        }
    }
    __syncthreads();

    if (tid < 128) {
        const int tok = tid;
        const uint4* hrow4 = reinterpret_cast<const uint4*>(
            reinterpret_cast<const char*>(hst) + tok * (HS * 2));

        float o_loc[12];
        #pragma unroll
        for (int i = 0; i < 12; i++) o_loc[i] = 0.0f;

        const int nu4 = ((lastc + 1) - col0) / 8;
        int hc = col0 - a0 * H_CNT;
        int ai = 0;
        for (int i = 0; i < nu4; i++) {
            const uint4 v = hrow4[i];
            uint32_t pr[4] = {v.x, v.y, v.z, v.w};
            #pragma unroll
            for (int p = 0; p < 4; p++) {
                float2 f = __half22float2(*reinterpret_cast<const __half2*>(&pr[p]));
                const float* wv = &W2s[ai * (H_CNT * O_CNT) + hc * O_CNT];
                o_loc[ai * 3 + 0] += f.x * wv[0] + f.y * wv[3];
                o_loc[ai * 3 + 1] += f.x * wv[1] + f.y * wv[4];
                o_loc[ai * 3 + 2] += f.x * wv[2] + f.y * wv[5];
                hc += 2;
                if (hc == H_CNT) { hc = 0; ai++; }
            }
        }

        const int tg = by * 128 + tok;
        #pragma unroll
        for (int q = 0; q < 4; q++) {
            const int a = a0 + q;
            if (a > a1v) break;
            const int slot = (q == 0 && a0 * H_CNT < col0) ? 1 : 0;
            float* dst = g_obuf[slot] + (size_t)tg * 60 + a * 3;
            dst[0] = o_loc[q * 3 + 0];
            dst[1] = o_loc[q * 3 + 1];
            dst[2] = o_loc[q * 3 + 2];
        }
    }
}

// =====================================================================
// K4: combine slots + squash; 4 tokens per warp (batched loads for MLP)
// =====================================================================
__global__ void __launch_bounds__(256) k_sq(const float* __restrict__ b2,
                                            float* __restrict__ out) {
    __shared__ float osm[32][64];
    __shared__ float scl[32][4];
    const int tid = threadIdx.x;
    const int w = tid >> 5, l = tid & 31;
    const int t0 = blockIdx.x * 32 + w * 4;     // first of 4 tokens for this warp

    // batched loads: 4 tokens x 2 positions in flight
    float v[4][2];
    #pragma unroll
    for (int r = 0; r < 2; r++) {
        const int p = l + r * 32;
        if (p < A_CNT * O_CNT) {
            const int a = p / 3;
            const int st = a * H_CNT;
            const bool split = (st >> 7) != ((st + H_CNT - 1) >> 7);
            const float bb = b2[p];
            #pragma unroll
            for (int j = 0; j < 4; j++) {
                const size_t t = (size_t)(t0 + j);
                float s = g_obuf[0][t * 60 + p];
                if (split) s += g_obuf[1][t * 60 + p];
                v[j][r] = s + bb;
            }
        }
    }
    #pragma unroll
    for (int r = 0; r < 2; r++) {
        const int p = l + r * 32;
        if (p < A_CNT * O_CNT)
            #pragma unroll
            for (int j = 0; j < 4; j++) osm[w * 4 + j][p] = v[j][r];
    }
    __syncwarp();

    if (l < O_CNT) {
        #pragma unroll
        for (int j = 0; j < 4; j++) {
            float sq = 0.0f;
            #pragma unroll
            for (int a = 0; a < A_CNT; a++) {
                float vv = osm[w * 4 + j][a * 3 + l];
                sq += vv * vv;
            }
            scl[w * 4 + j][l] = sqrtf(sq) / (1.0f + sq);
        }
    }
    __syncwarp();

    #pragma unroll
    for (int j = 0; j < 4; j++) {
        const int t = t0 + j;
        const int b = t >> 11, sidx = t & (S_LEN - 1);
        #pragma unroll
        for (int r = 0; r < 2; r++) {
            const int p = l + r * 32;
            if (p < A_CNT * O_CNT) {
                const int a = p / 3, jj = p - a * 3;
                out[(size_t)(b * A_CNT + a) * (S_LEN * O_CNT) + sidx * 3 + jj] =
                    osm[w * 4 + j][p] * scl[w * 4 + j][jj];
            }
        }
    }
}

// =====================================================================
// launch
// =====================================================================
extern "C" void kernel_launch(void* const* d_in, const int* in_sizes, int n_in,
                              void* d_out, int out_size) {
    (void)in_sizes; (void)n_in; (void)out_size;
    const float* x    = (const float*)d_in[0];
    const float* ln_g = (const float*)d_in[1];
    const float* ln_b = (const float*)d_in[2];
    const float* W1   = (const float*)d_in[3];
    const float* b1   = (const float*)d_in[4];
    const float* W2   = (const float*)d_in[5];
    const float* b2   = (const float*)d_in[6];
    float* out = (float*)d_out;

    cudaFuncSetAttribute(k_gemm, cudaFuncAttributeMaxDynamicSharedMemorySize, SMEMT);

    k_pre<<<NB_PRE, 256>>>(x, ln_g, ln_b, W1);
    k_off2<<<4, 256>>>(b1);
    k_gemm<<<dim3(8, 256), 256, SMEMT>>>(W2);
    k_sq<<<T_TOK / 32, 256>>>(b2, out);
}